// round 15
// baseline (speedup 1.0000x reference)
#include <cuda_runtime.h>
#include <cuda_bf16.h>

// ---------------------------------------------------------------------------
// RGCN link predictor:
//   Dual-stream fork-join (capture-safe): GEMM chain on capture stream
//   overlaps CSR chain (zero/count/scan/scatter) on a static second stream.
//   GEMM1: bf16 3-term compensated tensor-core, x-split fused into A-path
//   (reads fp32 x directly). GEMM2: same core, A from agg1's fused split.
//   agg2 fuses the UV decoder GEMM into its epilogue (shfl broadcast matvec).
//   decoder: cheap per-edge relu(U[s]+V[d]+b).Wd2.
// __device__ globals only referenced from device code (round-3 lesson).
// ---------------------------------------------------------------------------

#define NN    100000
#define REL   3
#define EMAX  1600000
#define SCAN_BS   256
#define SCAN_NB   ((NN + SCAN_BS - 1) / SCAN_BS)   // 391

// scratch (static device globals; no allocation allowed)
__device__ int      g_cnt[NN * REL];
__device__ float    g_inv[NN * REL];
__device__ int      g_off[NN + 1];
__device__ int      g_cur[NN];
__device__ int      g_bsum[SCAN_NB];
__device__ int      g_bpre[SCAN_NB];
__device__ unsigned g_epk[EMAX];     // src | (rel << 20), sorted by dst
__device__ float    g_H1[NN * 192];
__device__ float    g_Z1[NN * 64];
__device__ float    g_H2[NN * 96];
__device__ float    g_Z2[NN * 32];   // root part of layer-2 (gemm2 epilogue)
__device__ float    g_UV[NN * 128];  // cols 0-63: U, 64-127: V
__device__ float    g_Wd1c[32 * 128];
__device__ __nv_bfloat16 g_z1h[(size_t)NN * 64];
__device__ __nv_bfloat16 g_z1l[(size_t)NN * 64];
__device__ __nv_bfloat16 g_w1h[256 * 128];   // [n][k] transposed
__device__ __nv_bfloat16 g_w1l[256 * 128];
__device__ __nv_bfloat16 g_w2h[128 * 64];    // [n][k] transposed
__device__ __nv_bfloat16 g_w2l[128 * 64];

// ---------------------------------------------------------------------------
__global__ void zero_cnt_kernel(int n) {
    int i = blockIdx.x * blockDim.x + threadIdx.x;
    if (i < n) g_cnt[i] = 0;
}

// fused weight pack: W1 | W2 | Wd1
#define PREP_R1 (256 * 128)     // wt1
#define PREP_R2 (128 * 64)      // wt2
#define PREP_R3 (32 * 128)      // wd1c
#define PREP_TOT (PREP_R1 + PREP_R2 + PREP_R3)

__global__ void prep_w_kernel(const float* __restrict__ W1,
                              const float* __restrict__ root1,
                              const float* __restrict__ W2,
                              const float* __restrict__ root2,
                              const float* __restrict__ Wd1) {
    int i = blockIdx.x * blockDim.x + threadIdx.x;
    if (i < PREP_R1) {
        int n = i >> 7, k = i & 127;
        float w;
        if (n < 192) {
            int r = n >> 6, j = n & 63;
            w = W1[r * 128 * 64 + k * 64 + j];
        } else {
            w = root1[k * 64 + (n - 192)];
        }
        __nv_bfloat16 h = __float2bfloat16(w);
        g_w1h[i] = h;
        g_w1l[i] = __float2bfloat16(w - __bfloat162float(h));
        return;
    }
    i -= PREP_R1;
    if (i < PREP_R2) {
        int n = i >> 6, k = i & 63;
        float w;
        if (n < 96) {
            int r = n >> 5, j = n & 31;
            w = W2[r * 64 * 32 + k * 32 + j];
        } else {
            w = root2[k * 32 + (n - 96)];
        }
        __nv_bfloat16 h = __float2bfloat16(w);
        g_w2h[i] = h;
        g_w2l[i] = __float2bfloat16(w - __bfloat162float(h));
        return;
    }
    i -= PREP_R2;
    if (i < PREP_R3) {
        int k = i >> 7, c = i & 127;
        g_Wd1c[i] = (c < 64) ? Wd1[k * 64 + c] : Wd1[(32 + k) * 64 + (c - 64)];
    }
}

__global__ void count_kernel(const int* __restrict__ dst,
                             const int* __restrict__ et, int E) {
    int e = blockIdx.x * blockDim.x + threadIdx.x;
    if (e < E) atomicAdd(&g_cnt[dst[e] * 3 + et[e]], 1);
}

// ---- parallel 3-phase exclusive scan of node degrees (+ inv fused) --------
__global__ void __launch_bounds__(SCAN_BS) scan1_kernel() {
    __shared__ int s[SCAN_BS];
    int t = threadIdx.x;
    int i = blockIdx.x * SCAN_BS + t;
    int d = 0;
    if (i < NN) {
        int c0 = g_cnt[3 * i], c1 = g_cnt[3 * i + 1], c2 = g_cnt[3 * i + 2];
        d = c0 + c1 + c2;
        g_inv[3 * i]     = 1.0f / fmaxf((float)c0, 1.0f);
        g_inv[3 * i + 1] = 1.0f / fmaxf((float)c1, 1.0f);
        g_inv[3 * i + 2] = 1.0f / fmaxf((float)c2, 1.0f);
    }
    s[t] = d;
    __syncthreads();
#pragma unroll
    for (int o = 1; o < SCAN_BS; o <<= 1) {
        int v = (t >= o) ? s[t - o] : 0;
        __syncthreads();
        s[t] += v;
        __syncthreads();
    }
    if (i < NN) g_off[i] = s[t] - d;
    if (t == SCAN_BS - 1) g_bsum[blockIdx.x] = s[t];
}

__global__ void __launch_bounds__(512) scan2_kernel() {
    __shared__ int s[512];
    int t = threadIdx.x;
    int v0 = (t < SCAN_NB) ? g_bsum[t] : 0;
    s[t] = v0;
    __syncthreads();
#pragma unroll
    for (int o = 1; o < 512; o <<= 1) {
        int v = (t >= o) ? s[t - o] : 0;
        __syncthreads();
        s[t] += v;
        __syncthreads();
    }
    if (t < SCAN_NB) g_bpre[t] = s[t] - v0;
    if (t == 511) g_off[NN] = s[511];
}

__global__ void scan3_kernel() {
    int i = blockIdx.x * blockDim.x + threadIdx.x;
    if (i < NN) {
        int off = g_off[i] + g_bpre[i / SCAN_BS];
        g_off[i] = off;
        g_cur[i] = off;
    }
}

__global__ void scatter_kernel(const int* __restrict__ src,
                               const int* __restrict__ dst,
                               const int* __restrict__ et, int E) {
    int e = blockIdx.x * blockDim.x + threadIdx.x;
    if (e < E) {
        int pos = atomicAdd(&g_cur[dst[e]], 1);
        g_epk[pos] = (unsigned)src[e] | ((unsigned)et[e] << 20);
    }
}

// ---------------------------------------------------------------------------
// cp.async / ldmatrix helpers
// ---------------------------------------------------------------------------
__device__ __forceinline__ void cp_async16(void* smem_dst, const void* gmem_src) {
    unsigned saddr = (unsigned)__cvta_generic_to_shared(smem_dst);
    asm volatile("cp.async.cg.shared.global [%0], [%1], 16;\n"
                 :: "r"(saddr), "l"(gmem_src) : "memory");
}
__device__ __forceinline__ void cp_async_commit() {
    asm volatile("cp.async.commit_group;\n" ::: "memory");
}
__device__ __forceinline__ void cp_async_wait0() {
    asm volatile("cp.async.wait_group 0;\n" ::: "memory");
}
__device__ __forceinline__ void ldsm_x4(unsigned& r0, unsigned& r1,
                                        unsigned& r2, unsigned& r3,
                                        const void* p) {
    unsigned addr = (unsigned)__cvta_generic_to_shared(p);
    asm volatile("ldmatrix.sync.aligned.m8n8.x4.shared.b16 {%0,%1,%2,%3}, [%4];"
                 : "=r"(r0), "=r"(r1), "=r"(r2), "=r"(r3) : "r"(addr));
}

#define MMA_BF16(c, a0, a1, a2, a3, b0, b1)                                   \
    asm volatile(                                                             \
        "mma.sync.aligned.m16n8k16.row.col.f32.bf16.bf16.f32 "                \
        "{%0,%1,%2,%3}, {%4,%5,%6,%7}, {%8,%9}, {%0,%1,%2,%3};"               \
        : "+f"((c)[0]), "+f"((c)[1]), "+f"((c)[2]), "+f"((c)[3])              \
        : "r"(a0), "r"(a1), "r"(a2), "r"(a3), "r"(b0), "r"(b1))

// ---------------------------------------------------------------------------
// GEMM1: bf16 tensor-core, 3-term compensated, x-split fused into A-path.
// A: fp32 x staged through registers, split to bf16 hi/lo at smem store.
// B: resident panel (stride K+8). Block 128x128, BK=16, 8 warps (4m x 2n).
// ---------------------------------------------------------------------------
__global__ void __launch_bounds__(256, 2) gemm1_bf16_kernel(
    const float* __restrict__ x, const float* __restrict__ b1) {

    constexpr int K = 128, HCOLS = 192, ZW = 64;
    constexpr int BST = K + 8;
    extern __shared__ __align__(16) __nv_bfloat16 smem[];
    __nv_bfloat16* Ah = smem;                         // [2][128][24]
    __nv_bfloat16* Al = Ah + 2 * 128 * 24;
    __nv_bfloat16* Bh = Al + 2 * 128 * 24;            // [128][BST]
    __nv_bfloat16* Bl = Bh + 128 * BST;

    const int tid = threadIdx.x, lane = tid & 31, wid = tid >> 5;
    const int wm = wid & 3, wn = wid >> 2;
    const int g = lane >> 2, tg = lane & 3;
    const int m0 = blockIdx.y * 128, n0 = blockIdx.x * 128;
    const int row = tid >> 1, ch = tid & 1;

    const int aRow = lane & 15, aK = (lane >> 4) * 8;
    const int bRow = ((lane >> 4) * 8) + (lane & 7);
    const int bK8 = ((lane >> 3) & 1) * 8;

    float acc[2][8][4] = {};
    float4 aReg0, aReg1;

    auto loadA = [&](int k0) {
        int gr = min(m0 + row, NN - 1);
        const float* p = &x[(size_t)gr * 128 + k0 + ch * 8];
        aReg0 = *(const float4*)p;
        aReg1 = *(const float4*)(p + 4);
    };
    auto storeA = [&](int buf) {
        float f[8] = {aReg0.x, aReg0.y, aReg0.z, aReg0.w,
                      aReg1.x, aReg1.y, aReg1.z, aReg1.w};
        __align__(16) __nv_bfloat16 h[8], l[8];
#pragma unroll
        for (int j = 0; j < 8; j++) {
            h[j] = __float2bfloat16(f[j]);
            l[j] = __float2bfloat16(f[j] - __bfloat162float(h[j]));
        }
        *(uint4*)&Ah[(buf * 128 + row) * 24 + ch * 8] = *(uint4*)h;
        *(uint4*)&Al[(buf * 128 + row) * 24 + ch * 8] = *(uint4*)l;
    };

    // resident B panel (once)
    {
        constexpr int CHUNKS = K / 8;
        constexpr int ITERS = 128 * CHUNKS / 256;
#pragma unroll
        for (int it = 0; it < ITERS; it++) {
            int idx = tid + it * 256;
            int r = idx / CHUNKS, c = idx % CHUNKS;
            cp_async16(&Bh[r * BST + c * 8], &g_w1h[(n0 + r) * K + c * 8]);
            cp_async16(&Bl[r * BST + c * 8], &g_w1l[(n0 + r) * K + c * 8]);
        }
        cp_async_commit();
    }
    loadA(0);
    storeA(0);
    cp_async_wait0();
    __syncthreads();

    constexpr int KT = K / 16;
    int buf = 0;
#pragma unroll
    for (int kt = 0; kt < KT; kt++) {
        if (kt + 1 < KT) loadA((kt + 1) * 16);   // LDG in flight over compute

        const int kOff = kt * 16 + bK8;
        unsigned bh[8][2], bl[8][2];
#pragma unroll
        for (int njp = 0; njp < 4; njp++) {
            int nb = wn * 64 + njp * 16 + bRow;
            ldsm_x4(bh[njp * 2][0], bh[njp * 2][1],
                    bh[njp * 2 + 1][0], bh[njp * 2 + 1][1], &Bh[nb * BST + kOff]);
            ldsm_x4(bl[njp * 2][0], bl[njp * 2][1],
                    bl[njp * 2 + 1][0], bl[njp * 2 + 1][1], &Bl[nb * BST + kOff]);
        }
#pragma unroll
        for (int mi = 0; mi < 2; mi++) {
            int ar = wm * 32 + mi * 16 + aRow;
            unsigned ah0, ah1, ah2, ah3, al0, al1, al2, al3;
            ldsm_x4(ah0, ah1, ah2, ah3, &Ah[(buf * 128 + ar) * 24 + aK]);
            ldsm_x4(al0, al1, al2, al3, &Al[(buf * 128 + ar) * 24 + aK]);
#pragma unroll
            for (int nj = 0; nj < 8; nj++) {
                MMA_BF16(acc[mi][nj], ah0, ah1, ah2, ah3, bh[nj][0], bh[nj][1]);
                MMA_BF16(acc[mi][nj], ah0, ah1, ah2, ah3, bl[nj][0], bl[nj][1]);
                MMA_BF16(acc[mi][nj], al0, al1, al2, al3, bh[nj][0], bh[nj][1]);
            }
        }

        if (kt + 1 < KT) {
            storeA(buf ^ 1);       // other buffer: no hazard with compute(buf)
            __syncthreads();
            buf ^= 1;
        }
    }

#pragma unroll
    for (int mi = 0; mi < 2; mi++) {
#pragma unroll
        for (int nj = 0; nj < 8; nj++) {
            int r0 = m0 + wm * 32 + mi * 16 + g;
            int cb = n0 + wn * 64 + nj * 8 + 2 * tg;
            float* c = acc[mi][nj];
            if (cb >= HCOLS) {
                int zc = cb - HCOLS;
                float bx = b1[zc], by = b1[zc + 1];
                if (r0 < NN)
                    *(float2*)&g_Z1[(size_t)r0 * ZW + zc] =
                        make_float2(c[0] + bx, c[1] + by);
                if (r0 + 8 < NN)
                    *(float2*)&g_Z1[(size_t)(r0 + 8) * ZW + zc] =
                        make_float2(c[2] + bx, c[3] + by);
            } else {
                if (r0 < NN)
                    *(float2*)&g_H1[(size_t)r0 * HCOLS + cb] =
                        make_float2(c[0], c[1]);
                if (r0 + 8 < NN)
                    *(float2*)&g_H1[(size_t)(r0 + 8) * HCOLS + cb] =
                        make_float2(c[2], c[3]);
            }
        }
    }
}

// ---------------------------------------------------------------------------
// GEMM2: bf16 tensor-core core with bf16 A (from agg1's fused split).
// Resident B panel, double-buffered A via cp.async.
// ---------------------------------------------------------------------------
__global__ void __launch_bounds__(256, 2) gemm2_bf16_kernel(
    const float* __restrict__ b2) {

    constexpr int K = 64, HCOLS = 96, ZW = 32;
    constexpr int BST = K + 8;
    extern __shared__ __align__(16) __nv_bfloat16 smem[];
    __nv_bfloat16* Ah = smem;                         // [2][128][24]
    __nv_bfloat16* Al = Ah + 2 * 128 * 24;
    __nv_bfloat16* Bh = Al + 2 * 128 * 24;            // [128][BST]
    __nv_bfloat16* Bl = Bh + 128 * BST;

    const int tid = threadIdx.x, lane = tid & 31, wid = tid >> 5;
    const int wm = wid & 3, wn = wid >> 2;
    const int g = lane >> 2, tg = lane & 3;
    const int m0 = blockIdx.y * 128, n0 = blockIdx.x * 128;
    const int row = tid >> 1, ch = tid & 1;

    const int aRow = lane & 15, aK = (lane >> 4) * 8;
    const int bRow = ((lane >> 4) * 8) + (lane & 7);
    const int bK8 = ((lane >> 3) & 1) * 8;

    float acc[2][8][4] = {};

    auto issueA = [&](int k0, int buf) {
        int gr = min(m0 + row, NN - 1);
        cp_async16(&Ah[(buf * 128 + row) * 24 + ch * 8],
                   &g_z1h[(size_t)gr * K + k0 + ch * 8]);
        cp_async16(&Al[(buf * 128 + row) * 24 + ch * 8],
                   &g_z1l[(size_t)gr * K + k0 + ch * 8]);
        cp_async_commit();
    };

    {
        constexpr int CHUNKS = K / 8;
        constexpr int ITERS = 128 * CHUNKS / 256;
#pragma unroll
        for (int it = 0; it < ITERS; it++) {
            int idx = tid + it * 256;
            int r = idx / CHUNKS, c = idx % CHUNKS;
            cp_async16(&Bh[r * BST + c * 8], &g_w2h[(n0 + r) * K + c * 8]);
            cp_async16(&Bl[r * BST + c * 8], &g_w2l[(n0 + r) * K + c * 8]);
        }
    }
    issueA(0, 0);
    cp_async_wait0();
    __syncthreads();

    constexpr int KT = K / 16;
    int buf = 0;
#pragma unroll
    for (int kt = 0; kt < KT; kt++) {
        if (kt + 1 < KT) issueA((kt + 1) * 16, buf ^ 1);

        const int kOff = kt * 16 + bK8;
        unsigned bh[8][2], bl[8][2];
#pragma unroll
        for (int njp = 0; njp < 4; njp++) {
            int nb = wn * 64 + njp * 16 + bRow;
            ldsm_x4(bh[njp * 2][0], bh[njp * 2][1],
                    bh[njp * 2 + 1][0], bh[njp * 2 + 1][1], &Bh[nb * BST + kOff]);
            ldsm_x4(bl[njp * 2][0], bl[njp * 2][1],
                    bl[njp * 2 + 1][0], bl[njp * 2 + 1][1], &Bl[nb * BST + kOff]);
        }
#pragma unroll
        for (int mi = 0; mi < 2; mi++) {
            int ar = wm * 32 + mi * 16 + aRow;
            unsigned ah0, ah1, ah2, ah3, al0, al1, al2, al3;
            ldsm_x4(ah0, ah1, ah2, ah3, &Ah[(buf * 128 + ar) * 24 + aK]);
            ldsm_x4(al0, al1, al2, al3, &Al[(buf * 128 + ar) * 24 + aK]);
#pragma unroll
            for (int nj = 0; nj < 8; nj++) {
                MMA_BF16(acc[mi][nj], ah0, ah1, ah2, ah3, bh[nj][0], bh[nj][1]);
                MMA_BF16(acc[mi][nj], ah0, ah1, ah2, ah3, bl[nj][0], bl[nj][1]);
                MMA_BF16(acc[mi][nj], al0, al1, al2, al3, bh[nj][0], bh[nj][1]);
            }
        }

        if (kt + 1 < KT) {
            cp_async_wait0();
            __syncthreads();
            buf ^= 1;
        }
    }

#pragma unroll
    for (int mi = 0; mi < 2; mi++) {
#pragma unroll
        for (int nj = 0; nj < 8; nj++) {
            int r0 = m0 + wm * 32 + mi * 16 + g;
            int cb = n0 + wn * 64 + nj * 8 + 2 * tg;
            float* c = acc[mi][nj];
            if (cb >= HCOLS) {
                int zc = cb - HCOLS;
                float bx = b2[zc], by = b2[zc + 1];
                if (r0 < NN)
                    *(float2*)&g_Z2[(size_t)r0 * ZW + zc] =
                        make_float2(c[0] + bx, c[1] + by);
                if (r0 + 8 < NN)
                    *(float2*)&g_Z2[(size_t)(r0 + 8) * ZW + zc] =
                        make_float2(c[2] + bx, c[3] + by);
            } else {
                if (r0 < NN)
                    *(float2*)&g_H2[(size_t)r0 * HCOLS + cb] =
                        make_float2(c[0], c[1]);
                if (r0 + 8 < NN)
                    *(float2*)&g_H2[(size_t)(r0 + 8) * HCOLS + cb] =
                        make_float2(c[2], c[3]);
            }
        }
    }
}

#define GEMM1_SMEM (2 * 128 * 24 * 2 * 2 + 2 * 128 * (128 + 8) * 2)  // 94208
#define GEMM2_SMEM (2 * 128 * 24 * 2 * 2 + 2 * 128 * (64 + 8) * 2)   // 61440

// ---------------------------------------------------------------------------
// agg1: CSR warp-per-node, unroll-4; fuses Z1 += acc, relu, bf16 split.
// ---------------------------------------------------------------------------
__global__ void __launch_bounds__(256) agg1_csr_kernel() {
    int d = (blockIdx.x * blockDim.x + threadIdx.x) >> 5;
    int lane = threadIdx.x & 31;
    if (d >= NN) return;
    int beg = g_off[d], end = g_off[d + 1];
    float i0 = g_inv[3 * d], i1 = g_inv[3 * d + 1], i2 = g_inv[3 * d + 2];

    float2 acc = make_float2(0.f, 0.f);
    int i = beg;
    for (; i + 3 < end; i += 4) {
        unsigned v0 = g_epk[i],     v1 = g_epk[i + 1];
        unsigned v2 = g_epk[i + 2], v3 = g_epk[i + 3];
        int s0 = v0 & 0xFFFFF, r0 = v0 >> 20;
        int s1 = v1 & 0xFFFFF, r1 = v1 >> 20;
        int s2 = v2 & 0xFFFFF, r2 = v2 >> 20;
        int s3 = v3 & 0xFFFFF, r3 = v3 >> 20;
        float c0 = (r0 == 0) ? i0 : ((r0 == 1) ? i1 : i2);
        float c1 = (r1 == 0) ? i0 : ((r1 == 1) ? i1 : i2);
        float c2 = (r2 == 0) ? i0 : ((r2 == 1) ? i1 : i2);
        float c3 = (r3 == 0) ? i0 : ((r3 == 1) ? i1 : i2);
        float2 h0 = *(const float2*)&g_H1[(size_t)s0 * 192 + r0 * 64 + lane * 2];
        float2 h1 = *(const float2*)&g_H1[(size_t)s1 * 192 + r1 * 64 + lane * 2];
        float2 h2 = *(const float2*)&g_H1[(size_t)s2 * 192 + r2 * 64 + lane * 2];
        float2 h3 = *(const float2*)&g_H1[(size_t)s3 * 192 + r3 * 64 + lane * 2];
        acc.x += h0.x * c0 + h1.x * c1 + h2.x * c2 + h3.x * c3;
        acc.y += h0.y * c0 + h1.y * c1 + h2.y * c2 + h3.y * c3;
    }
    for (; i < end; i++) {
        unsigned v = g_epk[i];
        int s = v & 0xFFFFF, r = v >> 20;
        float sc = (r == 0) ? i0 : ((r == 1) ? i1 : i2);
        float2 h = *(const float2*)&g_H1[(size_t)s * 192 + r * 64 + lane * 2];
        acc.x += h.x * sc; acc.y += h.y * sc;
    }
    float2 z = *(const float2*)&g_Z1[(size_t)d * 64 + lane * 2];
    float zx = fmaxf(z.x + acc.x, 0.f);
    float zy = fmaxf(z.y + acc.y, 0.f);
    __nv_bfloat16 hx = __float2bfloat16(zx), hy = __float2bfloat16(zy);
    __nv_bfloat16 lx = __float2bfloat16(zx - __bfloat162float(hx));
    __nv_bfloat16 ly = __float2bfloat16(zy - __bfloat162float(hy));
    *(__nv_bfloat162*)&g_z1h[(size_t)d * 64 + lane * 2] = __nv_bfloat162(hx, hy);
    *(__nv_bfloat162*)&g_z1l[(size_t)d * 64 + lane * 2] = __nv_bfloat162(lx, ly);
}

// ---------------------------------------------------------------------------
// agg2 + fused UV matvec: warp owns node d, lane owns z2 col `lane`.
// After aggregation: UV[d][j] = sum_k z2[k] * Wd1c[k][j] via shfl broadcast;
// lane computes UV cols [lane*4, lane*4+4). No Z2 writeback needed.
// ---------------------------------------------------------------------------
__global__ void __launch_bounds__(256) agg2_uv_kernel() {
    __shared__ float sW[32 * 128];     // Wd1c
    {
        int t = threadIdx.x;
#pragma unroll
        for (int it = 0; it < 4; it++)
            ((float4*)sW)[t + it * 256] = ((const float4*)g_Wd1c)[t + it * 256];
    }
    __syncthreads();

    int d = (blockIdx.x * blockDim.x + threadIdx.x) >> 5;
    int lane = threadIdx.x & 31;
    if (d >= NN) return;
    int beg = g_off[d], end = g_off[d + 1];
    float i0 = g_inv[3 * d], i1 = g_inv[3 * d + 1], i2 = g_inv[3 * d + 2];

    float acc = 0.f;
    int i = beg;
    for (; i + 3 < end; i += 4) {
        unsigned v0 = g_epk[i],     v1 = g_epk[i + 1];
        unsigned v2 = g_epk[i + 2], v3 = g_epk[i + 3];
        int s0 = v0 & 0xFFFFF, r0 = v0 >> 20;
        int s1 = v1 & 0xFFFFF, r1 = v1 >> 20;
        int s2 = v2 & 0xFFFFF, r2 = v2 >> 20;
        int s3 = v3 & 0xFFFFF, r3 = v3 >> 20;
        float c0 = (r0 == 0) ? i0 : ((r0 == 1) ? i1 : i2);
        float c1 = (r1 == 0) ? i0 : ((r1 == 1) ? i1 : i2);
        float c2 = (r2 == 0) ? i0 : ((r2 == 1) ? i1 : i2);
        float c3 = (r3 == 0) ? i0 : ((r3 == 1) ? i1 : i2);
        float h0 = g_H2[(size_t)s0 * 96 + r0 * 32 + lane];
        float h1 = g_H2[(size_t)s1 * 96 + r1 * 32 + lane];
        float h2 = g_H2[(size_t)s2 * 96 + r2 * 32 + lane];
        float h3 = g_H2[(size_t)s3 * 96 + r3 * 32 + lane];
        acc += h0 * c0 + h1 * c1 + h2 * c2 + h3 * c3;
    }
    for (; i < end; i++) {
        unsigned v = g_epk[i];
        int s = v & 0xFFFFF, r = v >> 20;
        float sc = (r == 0) ? i0 : ((r == 1) ? i1 : i2);
        acc += g_H2[(size_t)s * 96 + r * 32 + lane] * sc;
    }
    float z2 = g_Z2[(size_t)d * 32 + lane] + acc;

    // UV matvec: broadcast each z2[k] across the warp
    float4 uv = make_float4(0.f, 0.f, 0.f, 0.f);
#pragma unroll
    for (int k = 0; k < 32; k++) {
        float zk = __shfl_sync(0xFFFFFFFFu, z2, k);
        float4 w = *(const float4*)&sW[k * 128 + lane * 4];
        uv.x += zk * w.x; uv.y += zk * w.y;
        uv.z += zk * w.z; uv.w += zk * w.w;
    }
    *(float4*)&g_UV[(size_t)d * 128 + lane * 4] = uv;
}

// ---------------------------------------------------------------------------
// per-edge decoder: out[p] = relu(U[s] + V[d] + bd1) . Wd2 + bd2
// ---------------------------------------------------------------------------
__global__ void __launch_bounds__(256) decoder2_kernel(
    const int* __restrict__ psrc, const int* __restrict__ pdst,
    const float* __restrict__ bd1, const float* __restrict__ Wd2,
    const float* __restrict__ bd2, float* __restrict__ out, int P) {
    __shared__ float sB1[64];
    __shared__ float sW2[64];
    int tid = threadIdx.x;
    if (tid < 64) { sB1[tid] = bd1[tid]; sW2[tid] = Wd2[tid]; }
    __syncthreads();

    int p = blockIdx.x * 256 + tid;
    if (p >= P) return;
    int s = psrc[p], d = pdst[p];
    const float* u = &g_UV[(size_t)s * 128];
    const float* v = &g_UV[(size_t)d * 128 + 64];

    float o = bd2[0];
#pragma unroll
    for (int q = 0; q < 16; q++) {
        float4 uu = *(const float4*)&u[q * 4];
        float4 vv = *(const float4*)&v[q * 4];
        float4 bb = *(const float4*)&sB1[q * 4];
        float4 ww = *(const float4*)&sW2[q * 4];
        o += fmaxf(uu.x + vv.x + bb.x, 0.f) * ww.x;
        o += fmaxf(uu.y + vv.y + bb.y, 0.f) * ww.y;
        o += fmaxf(uu.z + vv.z + bb.z, 0.f) * ww.z;
        o += fmaxf(uu.w + vv.w + bb.w, 0.f) * ww.w;
    }
    out[p] = o;
}

// ---------------------------------------------------------------------------
extern "C" void kernel_launch(void* const* d_in, const int* in_sizes, int n_in,
                              void* d_out, int out_size) {
    const float* x     = (const float*)d_in[0];
    const int*   ei    = (const int*)d_in[1];
    const int*   et    = (const int*)d_in[2];
    const int*   pe    = (const int*)d_in[3];
    const float* W1    = (const float*)d_in[4];
    const float* root1 = (const float*)d_in[5];
    const float* b1    = (const float*)d_in[6];
    const float* W2    = (const float*)d_in[7];
    const float* root2 = (const float*)d_in[8];
    const float* b2    = (const float*)d_in[9];
    const float* Wd1   = (const float*)d_in[10];
    const float* bd1   = (const float*)d_in[11];
    const float* Wd2   = (const float*)d_in[12];
    const float* bd2   = (const float*)d_in[13];
    float* out = (float*)d_out;

    const int E = in_sizes[1] / 2;
    const int P = in_sizes[3] / 2;
    const int* src = ei;
    const int* dst = ei + E;
    const int* ps  = pe;
    const int* pd  = pe + P;

    // one-time resources (created during the uncaptured correctness call;
    // reused unchanged during graph capture — no resource ops inside capture)
    static cudaStream_t s2 = nullptr;
    static cudaEvent_t evFork = nullptr, evJoin = nullptr;
    static bool attrDone = false;
    if (!attrDone) {
        cudaFuncSetAttribute(gemm1_bf16_kernel,
                             cudaFuncAttributeMaxDynamicSharedMemorySize, GEMM1_SMEM);
        cudaFuncSetAttribute(gemm2_bf16_kernel,
                             cudaFuncAttributeMaxDynamicSharedMemorySize, GEMM2_SMEM);
        cudaStreamCreateWithFlags(&s2, cudaStreamNonBlocking);
        cudaEventCreateWithFlags(&evFork, cudaEventDisableTiming);
        cudaEventCreateWithFlags(&evJoin, cudaEventDisableTiming);
        attrDone = true;
    }

    // ---- fork: CSR chain on s2, GEMM chain on capture stream ----
    cudaEventRecord(evFork, 0);
    cudaStreamWaitEvent(s2, evFork, 0);

    // stream s2: zero -> count -> scan(inv) -> scatter
    zero_cnt_kernel<<<(NN * 3 + 255) / 256, 256, 0, s2>>>(NN * 3);
    count_kernel<<<(E + 255) / 256, 256, 0, s2>>>(dst, et, E);
    scan1_kernel<<<SCAN_NB, SCAN_BS, 0, s2>>>();
    scan2_kernel<<<1, 512, 0, s2>>>();
    scan3_kernel<<<(NN + 255) / 256, 256, 0, s2>>>();
    scatter_kernel<<<(E + 255) / 256, 256, 0, s2>>>(src, dst, et, E);
    cudaEventRecord(evJoin, s2);

    // capture stream: pack weights -> gemm1 (x-split fused)
    prep_w_kernel<<<(PREP_TOT + 255) / 256, 256>>>(W1, root1, W2, root2, Wd1);
    {
        dim3 g(2, (NN + 127) / 128);
        gemm1_bf16_kernel<<<g, 256, GEMM1_SMEM>>>(x, b1);
    }

    // ---- join ----
    cudaStreamWaitEvent(0, evJoin, 0);

    // layer 1 aggregation (fused relu + bf16 split for layer 2)
    agg1_csr_kernel<<<(NN * 32 + 255) / 256, 256>>>();

    // layer 2 (bf16 tensor core)
    {
        dim3 g(1, (NN + 127) / 128);
        gemm2_bf16_kernel<<<g, 256, GEMM2_SMEM>>>(b2);
    }

    // layer-2 aggregation with fused UV decoder GEMM
    agg2_uv_kernel<<<(NN * 32 + 255) / 256, 256>>>();

    // per-edge decoder
    decoder2_kernel<<<(P + 255) / 256, 256>>>(ps, pd, bd1, Wd2, bd2, out, P);
}